// round 1
// baseline (speedup 1.0000x reference)
#include <cuda_runtime.h>

namespace {
constexpr int T_  = 1024;
constexpr int S_  = 64;
constexpr int D_  = 256;
constexpr int TP_ = 8;
constexpr int C_  = 65;   // 2*H*N_K + 1
}

// Runtime flag: 1 if loc/rand inputs are int64 (we then read the low 32-bit word).
__device__ int g_is64;

__global__ void detect_is64(const int* __restrict__ w) {
    int lane = threadIdx.x;
    bool ok = true;
    #pragma unroll
    for (int i = 0; i < 8; i++) {
        int idx = lane + 32 * i;          // 256 candidate int64 elements -> 512 words (fits int32 case: 8192 words)
        int lo = w[2 * idx];
        int hi = w[2 * idx + 1];
        ok = ok && (hi == (lo >> 31));    // int64 low/high word pattern
    }
    unsigned m = __ballot_sync(0xffffffffu, ok);
    if (lane == 0) g_is64 = (m == 0xffffffffu) ? 1 : 0;
}

__global__ __launch_bounds__(256, 1) void crit_main(
    const int*   __restrict__ sta_loc,
    const int*   __restrict__ nei_loc,
    const int*   __restrict__ rand_numbers,
    const float* __restrict__ sta_emb,
    const float* __restrict__ nei_emb,
    const float* __restrict__ mask,
    const float* __restrict__ rand_vals,
    const float* __restrict__ t_rand,
    float*       __restrict__ out)
{
    __shared__ float    s_sta[D_];
    __shared__ float    s_eu[S_];
    __shared__ float    s_mask[S_];
    __shared__ float    s_w[S_];
    __shared__ float    s_cs[S_][TP_];
    __shared__ float    s_B[S_][TP_];
    __shared__ int      s_nei[S_][TP_];     // packed (abs<<1)|sign
    __shared__ unsigned s_cnc[C_][TP_];     // packed (abs<<1)|sign
    __shared__ float    s_loss[C_][TP_];
    __shared__ float    s_red[8];
    __shared__ float    s_rns, s_lth;
    __shared__ int      s_staloc[TP_];
    __shared__ float    s_rv[TP_];
    __shared__ float    s_rl[TP_];

    const int t    = blockIdx.x;
    const int tid  = threadIdx.x;
    const int lane = tid & 31;
    const int warp = tid >> 5;
    const int str  = g_is64 ? 2 : 1;

    // ---------- Phase A: sta row + norm^2, mask, scalars ----------
    float sv = sta_emb[(size_t)t * D_ + tid];
    s_sta[tid] = sv;
    float ns = sv * sv;
    #pragma unroll
    for (int o = 16; o; o >>= 1) ns += __shfl_xor_sync(0xffffffffu, ns, o);
    if (lane == 0) s_red[warp] = ns;
    if (tid < S_)  s_mask[tid] = mask[(size_t)t * S_ + tid];
    if (tid < TP_) {
        s_staloc[tid] = sta_loc[((size_t)t * TP_ + tid) * str];
        s_rv[tid]     = rand_vals[(size_t)t * TP_ + tid];
    }
    __syncthreads();

    if (tid < 32) {
        float m = s_mask[tid] + s_mask[tid + 32];
        #pragma unroll
        for (int o = 16; o; o >>= 1) m += __shfl_xor_sync(0xffffffffu, m, o);
        if (tid == 0) {
            s_lth = m + 1e-12f;
            float tot = 0.f;
            #pragma unroll
            for (int i = 0; i < 8; i++) tot += s_red[i];
            s_rns = rsqrtf(tot);
        }
    }
    __syncthreads();

    // ---------- Phase B: eu[s] = dot(sta, nei_s) / (|sta||nei_s|), 8 rows/warp ----------
    {
        const float4* sa = (const float4*)s_sta;
        float4 a0 = sa[lane];
        float4 a1 = sa[lane + 32];
        float rns = s_rns;
        #pragma unroll
        for (int k = 0; k < 8; k++) {
            int s = warp * 8 + k;
            const float4* row = (const float4*)(nei_emb + ((size_t)t * S_ + s) * D_);
            float4 b0 = row[lane];
            float4 b1 = row[lane + 32];
            float dot = a0.x*b0.x + a0.y*b0.y + a0.z*b0.z + a0.w*b0.w
                      + a1.x*b1.x + a1.y*b1.y + a1.z*b1.z + a1.w*b1.w;
            float nn  = b0.x*b0.x + b0.y*b0.y + b0.z*b0.z + b0.w*b0.w
                      + b1.x*b1.x + b1.y*b1.y + b1.z*b1.z + b1.w*b1.w;
            #pragma unroll
            for (int o = 16; o; o >>= 1) {
                dot += __shfl_xor_sync(0xffffffffu, dot, o);
                nn  += __shfl_xor_sync(0xffffffffu, nn,  o);
            }
            if (lane == 0) s_eu[s] = dot * rsqrtf(nn) * rns;
        }
    }

    // ---------- Phase D: cos_sn[s][p] + packed nei ----------
    #pragma unroll
    for (int it = 0; it < 2; it++) {
        int idx = tid + it * 256;           // 512 (s,p) pairs
        int s = idx >> 3, p = idx & 7;
        int nb = nei_loc[(((size_t)t * S_ + s) * TP_ + p) * str];
        int sl = s_staloc[p];
        int sg = ((nb ^ sl) < 0);           // sign(a)!=sign(b)  (a>=0 vs b>=0)
        int na = nb < 0 ? -nb : nb;
        int aa = sl < 0 ? -sl : sl;
        unsigned x = (unsigned)(na ^ aa) + 1u;
        int v  = __clz((int)x) - 16;        // = 16 - bitlen(x)
        int iv = sg ? -v : v;
        s_cs[s][p]  = (float)iv * 0.0625f;  // cos_sim value
        s_nei[s][p] = (na << 1) | (nb < 0 ? 1 : 0);
    }

    // ---------- Phase E: cnc_loc packed ----------
    for (int idx = tid; idx < C_ * TP_; idx += 256) {
        int c = idx >> 3, p = idx & 7;
        int sl = s_staloc[p];
        int val;
        if (c == 32) {
            val = sl;
        } else {
            int cc = (c < 32) ? c : (c - 33);
            int k = cc >> 1, j = cc & 1;
            int rn = rand_numbers[((((size_t)t * 16 + k) * 2 + j) * TP_ + p) * str];
            int r = sl ^ (1 << k) ^ (rn & ((1 << k) - 1));
            val = (c < 32) ? r : -r;
        }
        int av = val < 0 ? -val : val;
        s_cnc[c][p] = ((unsigned)av << 1) | (val < 0 ? 1u : 0u);
    }
    __syncthreads();

    // ---------- Phase C': B[s][p] = (sum_p cs - cs)/8 - eu ;  w[s] = |eu|*mask/lth ----------
    if (tid < S_) {
        int s = tid;
        float sum = 0.f;
        #pragma unroll
        for (int p = 0; p < 8; p++) sum += s_cs[s][p];
        float eu = s_eu[s];
        s_w[s] = fabsf(eu) * s_mask[s] / s_lth;
        #pragma unroll
        for (int p = 0; p < 8; p++)
            s_B[s][p] = (sum - s_cs[s][p]) * 0.125f - eu;
    }
    __syncthreads();

    // ---------- Phase F: loss[c][p] = sum_s w[s] * (B[s][p] + cos_cn/8)^2 ----------
    for (int idx = tid; idx < C_ * TP_; idx += 256) {
        int c = idx >> 3, p = idx & 7;
        unsigned ca = s_cnc[c][p];
        float acc = 0.f;
        #pragma unroll 8
        for (int s = 0; s < S_; s++) {
            unsigned y = ca ^ (unsigned)s_nei[s][p];
            int sg = (int)(y & 1u);
            unsigned x = (y >> 1) + 1u;     // |a|^|b| + 1
            int v  = __clz((int)x) - 16;
            int iv = sg ? -v : v;
            float f = fmaf((float)iv, 0.0078125f, s_B[s][p]);  // /128 = (1/16)/TP
            acc = fmaf(s_w[s], f * f, acc);
        }
        s_loss[c][p] = acc;
    }
    __syncthreads();

    // ---------- Phase G: argmin, selection, outputs ----------
    if (tid < TP_) {
        int p = tid;
        float best = s_loss[0][p]; int bc = 0;
        #pragma unroll
        for (int c = 1; c < C_; c++) {
            float v = s_loss[c][p];
            if (v < best) { best = v; bc = c; }   // first-occurrence argmin
        }
        // stable-argsort rank of rand_vals[p]
        float rv = s_rv[p]; int rank = 0;
        #pragma unroll
        for (int q = 0; q < 8; q++) {
            float o = s_rv[q];
            rank += (o < rv) || (o == rv && q < p);
        }
        int selg = (t_rand[t] < 0.8f);
        int ci = (rank < 4) ? (selg ? bc : 32) : 32;
        unsigned pk = s_cnc[ci][p];
        int val = (pk & 1u) ? -(int)(pk >> 1) : (int)(pk >> 1);
        out[(size_t)t * TP_ + p] = (float)val;
        s_rl[p] = s_loss[ci][p];
        __syncwarp(0x000000ffu);
        if (p == 0) {
            float rl = 0.f;
            #pragma unroll
            for (int q = 0; q < 8; q++) rl += s_rl[q];
            out[(size_t)T_ * TP_ + t] = rl * 0.125f;
        }
    }
}

extern "C" void kernel_launch(void* const* d_in, const int* in_sizes, int n_in,
                              void* d_out, int out_size) {
    (void)in_sizes; (void)n_in; (void)out_size;
    const int*   sta_loc      = (const int*)  d_in[0];
    const int*   nei_loc      = (const int*)  d_in[1];
    const int*   rand_numbers = (const int*)  d_in[2];
    const float* sta_emb      = (const float*)d_in[3];
    const float* nei_emb      = (const float*)d_in[4];
    const float* mask         = (const float*)d_in[5];
    const float* rand_vals    = (const float*)d_in[6];
    const float* t_rand       = (const float*)d_in[7];
    float* out = (float*)d_out;

    detect_is64<<<1, 32>>>(sta_loc);
    crit_main<<<T_, 256>>>(sta_loc, nei_loc, rand_numbers,
                           sta_emb, nei_emb, mask, rand_vals, t_rand, out);
}

// round 2
// speedup vs baseline: 1.6452x; 1.6452x over previous
#include <cuda_runtime.h>

namespace {
constexpr int T_  = 1024;
constexpr int S_  = 64;
constexpr int D_  = 256;
constexpr int TP_ = 8;
constexpr int C_  = 65;   // 2*H*N_K + 1
}

// Runtime flag: 1 if loc/rand inputs are int64 (we then read the low 32-bit word).
__device__ int g_is64;

__global__ void detect_is64(const int* __restrict__ w) {
    int lane = threadIdx.x;
    bool ok = true;
    #pragma unroll
    for (int i = 0; i < 8; i++) {
        int idx = lane + 32 * i;
        int lo = w[2 * idx];
        int hi = w[2 * idx + 1];
        ok = ok && (hi == (lo >> 31));
    }
    unsigned m = __ballot_sync(0xffffffffu, ok);
    if (lane == 0) g_is64 = (m == 0xffffffffu) ? 1 : 0;
}

__device__ __forceinline__ unsigned pack_sgnabs(int v) {
    unsigned a = (unsigned)(v < 0 ? -v : v);
    return a | (v < 0 ? 0x80000000u : 0u);
}

__global__ __launch_bounds__(256, 3) void crit_main(
    const int*   __restrict__ sta_loc,
    const int*   __restrict__ nei_loc,
    const int*   __restrict__ rand_numbers,
    const float* __restrict__ sta_emb,
    const float* __restrict__ nei_emb,
    const float* __restrict__ mask,
    const float* __restrict__ rand_vals,
    const float* __restrict__ t_rand,
    float*       __restrict__ out)
{
    __shared__ float    s_sta[D_];
    __shared__ float    s_eu[S_];
    __shared__ float    s_mask[S_];
    __shared__ float    s_cs[S_][TP_];
    __shared__ unsigned s_neiT[TP_][68];   // transposed, padded: packed (sign<<31)|abs
    __shared__ float    s_PT[TP_][68];     // sqrt(w_s) * B[s][p], transposed, padded
    __shared__ float    s_swc[68];         // sqrt(w_s)/128
    __shared__ unsigned s_cnc[C_][TP_];    // packed (sign<<31)|abs
    __shared__ float    s_loss[C_][TP_];
    __shared__ float    s_red[8];
    __shared__ float    s_l32[2];
    __shared__ float    s_rns, s_invlth;
    __shared__ int      s_staloc[TP_];
    __shared__ float    s_rv[TP_];
    __shared__ float    s_rl[TP_];

    const int t    = blockIdx.x;
    const int tid  = threadIdx.x;
    const int lane = tid & 31;
    const int warp = tid >> 5;
    const int str  = g_is64 ? 2 : 1;

    // ---------------- Head: issue all small LDGs up front ----------------
    float sv  = sta_emb[(size_t)t * D_ + tid];
    int   nb0 = nei_loc[((size_t)t * (S_*TP_) + tid) * str];
    int   nb1 = nei_loc[((size_t)t * (S_*TP_) + 256 + tid) * str];
    int   rn  = rand_numbers[((size_t)t * 256 + tid) * str];
    float tr  = 0.f;
    if (tid < S_)  s_mask[tid] = mask[(size_t)t * S_ + tid];
    if (tid < TP_) {
        s_staloc[tid] = sta_loc[((size_t)t * TP_ + tid) * str];
        s_rv[tid]     = rand_vals[(size_t)t * TP_ + tid];
        tr            = t_rand[t];
    }
    s_sta[tid] = sv;
    float ns = sv * sv;
    #pragma unroll
    for (int o = 16; o; o >>= 1) ns += __shfl_xor_sync(0xffffffffu, ns, o);
    if (lane == 0) s_red[warp] = ns;
    __syncthreads();

    // ---------------- A2 (warp 0): 1/lth, rsqrt(|sta|^2) ----------------
    if (tid < 32) {
        float m = s_mask[tid] + s_mask[tid + 32];
        #pragma unroll
        for (int o = 16; o; o >>= 1) m += __shfl_xor_sync(0xffffffffu, m, o);
        if (tid == 0) {
            s_invlth = 1.0f / (m + 1e-12f);
            float tot = 0.f;
            #pragma unroll
            for (int i = 0; i < 8; i++) tot += s_red[i];
            s_rns = rsqrtf(tot);
        }
    }

    // ---------------- D: cos_sn + packed nei (transposed) ----------------
    {
        #pragma unroll
        for (int it = 0; it < 2; it++) {
            int idx = tid + it * 256;
            int nb  = it ? nb1 : nb0;
            int s = idx >> 3, p = idx & 7;
            int sl = s_staloc[p];
            int sg = ((nb ^ sl) < 0);
            int na = nb < 0 ? -nb : nb;
            int aa = sl < 0 ? -sl : sl;
            unsigned x = (unsigned)(na ^ aa) + 1u;
            int v  = __clz((int)x) - 16;
            int iv = sg ? -v : v;
            s_cs[s][p]   = (float)iv * 0.0625f;
            s_neiT[p][s] = (unsigned)na | (nb < 0 ? 0x80000000u : 0u);
        }
    }

    // ---------------- E: cnc packed ----------------
    {
        int k = tid >> 4, p = tid & 7, c = tid >> 3;   // c = 2k+j
        int sl = s_staloc[p];
        int r = sl ^ (1 << k) ^ (rn & ((1 << k) - 1));
        s_cnc[c][p]      = pack_sgnabs(r);
        s_cnc[c + 33][p] = pack_sgnabs(-r);
        if (tid < TP_) s_cnc[32][tid] = pack_sgnabs(s_staloc[tid]);
    }
    __syncthreads();

    // ---------------- B: eu[s], 8 lanes per row, 4 rows/warp/iter ----------------
    {
        int q = lane & 7;
        const float4* sa = (const float4*)s_sta;
        #pragma unroll
        for (int it = 0; it < 2; it++) {
            int row = warp * 8 + it * 4 + (lane >> 3);
            const float4* nr = (const float4*)(nei_emb + ((size_t)t * S_ + row) * D_);
            float4 b[8];
            #pragma unroll
            for (int j = 0; j < 8; j++) b[j] = nr[q + 8 * j];
            float dot = 0.f, nn = 0.f;
            #pragma unroll
            for (int j = 0; j < 8; j++) {
                float4 a = sa[q + 8 * j];
                float4 bb = b[j];
                dot = fmaf(a.x, bb.x, dot); dot = fmaf(a.y, bb.y, dot);
                dot = fmaf(a.z, bb.z, dot); dot = fmaf(a.w, bb.w, dot);
                nn  = fmaf(bb.x, bb.x, nn); nn  = fmaf(bb.y, bb.y, nn);
                nn  = fmaf(bb.z, bb.z, nn); nn  = fmaf(bb.w, bb.w, nn);
            }
            #pragma unroll
            for (int o = 1; o < 8; o <<= 1) {
                dot += __shfl_xor_sync(0xffffffffu, dot, o);
                nn  += __shfl_xor_sync(0xffffffffu, nn,  o);
            }
            if (q == 0) s_eu[row] = dot * rsqrtf(nn) * s_rns;
        }
    }
    __syncthreads();

    // ---------------- C': P = sqw*B, swc = sqw/128, loss32 ----------------
    if (tid < S_) {
        int s = tid;
        float4 ca = *(const float4*)&s_cs[s][0];
        float4 cb = *(const float4*)&s_cs[s][4];
        float sum = ca.x + ca.y + ca.z + ca.w + cb.x + cb.y + cb.z + cb.w;
        float eu  = s_eu[s];
        float w   = fabsf(eu) * s_mask[s] * s_invlth;
        float sqw = sqrtf(w);
        s_swc[s]  = sqw * 0.0078125f;
        float cm  = fmaf(sum, 0.125f, -eu);            // sum/8 - eu
        float csv[8] = {ca.x, ca.y, ca.z, ca.w, cb.x, cb.y, cb.z, cb.w};
        #pragma unroll
        for (int p = 0; p < 8; p++)
            s_PT[p][s] = sqw * fmaf(csv[p], -0.125f, cm);   // sqw * B[s][p]
        float t32 = w * cm * cm;
        #pragma unroll
        for (int o = 16; o; o >>= 1) t32 += __shfl_xor_sync(0xffffffffu, t32, o);
        if (lane == 0) s_l32[warp] = t32;
    }
    __syncthreads();

    // ---------------- F: loss[c][p], two c's per thread ----------------
    {
        int p  = tid & 7;
        int c0 = tid >> 3;                  // 0..31
        unsigned ca0 = s_cnc[c0][p];
        unsigned ca1 = s_cnc[c0 + 33][p];
        float acc0 = 0.f, acc1 = 0.f;
        const int4*   nt  = (const int4*)&s_neiT[p][0];
        const float4* ptv = (const float4*)&s_PT[p][0];
        const float4* swp = (const float4*)s_swc;
        #pragma unroll
        for (int s4 = 0; s4 < 16; s4++) {
            int4   nv = nt[s4];
            float4 Pv = ptv[s4];
            float4 sw = swp[s4];
            #pragma unroll
            for (int i = 0; i < 4; i++) {
                unsigned ne = (i == 0) ? (unsigned)nv.x : (i == 1) ? (unsigned)nv.y
                            : (i == 2) ? (unsigned)nv.z : (unsigned)nv.w;
                float P  = (i == 0) ? Pv.x : (i == 1) ? Pv.y : (i == 2) ? Pv.z : Pv.w;
                float swv = (i == 0) ? sw.x : (i == 1) ? sw.y : (i == 2) ? sw.z : sw.w;
                // c0 chain
                {
                    unsigned xm = (ca0 ^ ne) & 0x1FFFFu;
                    unsigned gs = (ca0 ^ ne) & 0x80000000u;
                    float uf = (float)(__clz((int)(xm + 1u)) - 16);
                    float us = __int_as_float(__float_as_int(uf) ^ gs);
                    float h  = fmaf(us, swv, P);
                    acc0 = fmaf(h, h, acc0);
                }
                // c1 chain
                {
                    unsigned xm = (ca1 ^ ne) & 0x1FFFFu;
                    unsigned gs = (ca1 ^ ne) & 0x80000000u;
                    float uf = (float)(__clz((int)(xm + 1u)) - 16);
                    float us = __int_as_float(__float_as_int(uf) ^ gs);
                    float h  = fmaf(us, swv, P);
                    acc1 = fmaf(h, h, acc1);
                }
            }
        }
        s_loss[c0][p]      = acc0;
        s_loss[c0 + 33][p] = acc1;
        if (tid < TP_) s_loss[32][tid] = s_l32[0] + s_l32[1];   // loss[32][p] is p-independent
    }
    __syncthreads();

    // ---------------- G: argmin, selection, outputs ----------------
    if (tid < TP_) {
        int p = tid;
        float best = s_loss[0][p]; int bc = 0;
        #pragma unroll
        for (int c = 1; c < C_; c++) {
            float v = s_loss[c][p];
            if (v < best) { best = v; bc = c; }      // first-occurrence argmin
        }
        float rv = s_rv[p]; int rank = 0;
        #pragma unroll
        for (int q = 0; q < 8; q++) {
            float o = s_rv[q];
            rank += (o < rv) || (o == rv && q < p);  // stable argsort rank
        }
        int selg = (tr < 0.8f);
        int ci = (rank < 4) ? (selg ? bc : 32) : 32;
        unsigned pk = s_cnc[ci][p];
        int val = (pk & 0x80000000u) ? -(int)(pk & 0x7fffffffu) : (int)pk;
        out[(size_t)t * TP_ + p] = (float)val;
        s_rl[p] = s_loss[ci][p];
        __syncwarp(0x000000ffu);
        if (p == 0) {
            float rl = 0.f;
            #pragma unroll
            for (int q = 0; q < 8; q++) rl += s_rl[q];
            out[(size_t)T_ * TP_ + t] = rl * 0.125f;
        }
    }
}

extern "C" void kernel_launch(void* const* d_in, const int* in_sizes, int n_in,
                              void* d_out, int out_size) {
    (void)in_sizes; (void)n_in; (void)out_size;
    const int*   sta_loc      = (const int*)  d_in[0];
    const int*   nei_loc      = (const int*)  d_in[1];
    const int*   rand_numbers = (const int*)  d_in[2];
    const float* sta_emb      = (const float*)d_in[3];
    const float* nei_emb      = (const float*)d_in[4];
    const float* mask         = (const float*)d_in[5];
    const float* rand_vals    = (const float*)d_in[6];
    const float* t_rand       = (const float*)d_in[7];
    float* out = (float*)d_out;

    detect_is64<<<1, 32>>>(sta_loc);
    crit_main<<<T_, 256>>>(sta_loc, nei_loc, rand_numbers,
                           sta_emb, nei_emb, mask, rand_vals, t_rand, out);
}